// round 14
// baseline (speedup 1.0000x reference)
#include <cuda_runtime.h>
#include <cuda_bf16.h>
#include <cstdint>

#define NB   32
#define CC   128
#define HH_  56
#define WW_  56

// activations int8, packed: [n][chunk 4][h 56][w' 64][ci 32] (w'=w+1, zero cols 0,57-63)
__device__ uint32_t g_xq [NB*4*HH_*64*8];
__device__ uint32_t g_y1q[NB*4*HH_*64*8];
// weights int8, PRE-PERMUTED for per-lane LDS.64 B fragments:
// [T 2][ch 4][tap 9][cg 2][j 8][lane 32][2 words]
__device__ uint32_t g_wq [2*4*9*2*8*32*2];

// ---------------- prep: quantize x -> packed int8 ---------------------------
__global__ void prep_x(const float* __restrict__ x) {
    __shared__ char s[CC][WW_];
    const int h = blockIdx.x, n = blockIdx.y, t = threadIdx.x;
    for (int i = t; i < CC*WW_; i += 256) {
        int c = i / WW_, w = i % WW_;
        float v = x[((n*CC + c)*HH_ + h)*WW_ + w];
        s[c][w] = (char)(int)rintf(fminf(fmaxf(v * 32.0f, -128.0f), 127.0f));
    }
    __syncthreads();
    for (int i = t; i < 4*64*8; i += 256) {
        int u = i & 7, wp = (i >> 3) & 63, ch = i >> 9;
        uint32_t word = 0;
        if (wp >= 1 && wp <= 56) {
            int ci = ch*32 + u*4, w = wp - 1;
            word = ((uint32_t)(uint8_t)s[ci][w])
                 | ((uint32_t)(uint8_t)s[ci+1][w] << 8)
                 | ((uint32_t)(uint8_t)s[ci+2][w] << 16)
                 | ((uint32_t)(uint8_t)s[ci+3][w] << 24);
        }
        g_xq[(((n*4 + ch)*HH_ + h)*64 + wp)*8 + u] = word;
    }
}

// ---------------- prep: weights OIHW f32 -> permuted int8 fragments ---------
// word e -> [T][ch][tap][cg 2][j 8][lane l][w2]
__global__ void prep_w(const float* __restrict__ w1, const float* __restrict__ w2s) {
    int e = blockIdx.x*256 + threadIdx.x;
    if (e >= 2*4*9*2*8*32*2) return;
    int w2 = e & 1, l = (e >> 1) & 31, j = (e >> 6) & 7, cg = (e >> 9) & 1;
    int g  = e >> 10;
    int tap = g % 9, ch = (g / 9) & 3, T = g / 36;
    const float* w = T ? w2s : w1;
    int co = cg*64 + j*8 + (l >> 2);
    int ciw = (l & 3) + w2*4;
    uint32_t word = 0;
#pragma unroll
    for (int b = 0; b < 4; ++b) {
        int ci = ch*32 + ciw*4 + b;
        int q = (int)rintf(w[(co*CC + ci)*9 + tap]);
        word |= (uint32_t)(q & 255) << (8*b);
    }
    g_wq[e] = word;
}

// ---------------- conv core: int8 mma m16n8k32, M32 x N64, occ-3 ------------
// block: n (z), cout-group of 64 (y of 2), 4 h-rows (x of 14). 8 warps:
//   warp -> (row hh = wid>>1, w-half ws = wid&1), warp tile M=32 pix x N=64 cout
// per tap: 2 ldmatrix + 8 LDS.64 + 16 mma (192 B smem / mma).
// 48B pad before X: p=-1 lands in pad, p=64 in W region; both feed only
// discarded output columns (per-lane accumulators keep them isolated).
static const int XS_BYTES = 6*64*48;            // 18432
static const int WS_BYTES = 9*8*32*8;           // 18432
static const int SM_BYTES = 48 + XS_BYTES + WS_BYTES;   // 36912 static

template <int PHASE>
__global__ void __launch_bounds__(256, 3)
conv_imma(const float* __restrict__ xres, float* __restrict__ out) {
    __shared__ __align__(16) char smem[SM_BYTES];
    char* Xs = smem + 48;
    char* Ws = Xs + XS_BYTES;
    const uint4* gin4 = (const uint4*)(PHASE == 0 ? g_xq : g_y1q);
    const uint4* gw4  = (const uint4*)g_wq + (size_t)PHASE*(4*9*2*512/4);

    const int n = blockIdx.z, cg = blockIdx.y, h0 = blockIdx.x*4;
    const int t = threadIdx.x, wid = t >> 5, l = t & 31;
    const int hh = wid >> 1, ws = wid & 1;
    const uint32_t Xu = (uint32_t)__cvta_generic_to_shared(Xs);

    // hoisted A base addresses (no clamp; pad absorbs p=-1, W region p=64)
    uint32_t Ab[2];
#pragma unroll
    for (int i = 0; i < 2; ++i)
        Ab[i] = Xu + (hh*64 + ws*32 + i*16 + (l & 15) - 1)*48 + (l >> 4)*16;

    int c[2][8][4];
#pragma unroll
    for (int i = 0; i < 2; ++i)
#pragma unroll
        for (int j = 0; j < 8; ++j)
#pragma unroll
            for (int k = 0; k < 4; ++k) c[i][j][k] = 0;

    for (int ch = 0; ch < 4; ++ch) {
        __syncthreads();
        // stage X: 6 rows (h0-1 .. h0+4) x 64 w', 32B/pixel -> 48B rows
        for (int i = t; i < 384; i += 256) {
            int hr = i >> 6, w = i & 63;
            int h = h0 + hr - 1;
            uint4 v0 = make_uint4(0,0,0,0), v1 = v0;
            if (h >= 0 && h < HH_) {
                const uint4* p = gin4 + ((((n*4 + ch)*HH_ + h)*64 + w) << 1);
                v0 = p[0]; v1 = p[1];
            }
            char* d = Xs + (hr*64 + w)*48;
            *(uint4*)d        = v0;
            *(uint4*)(d + 16) = v1;
        }
        // stage W: contiguous permuted fragments, 128 uint4 per tap
        for (int i = t; i < 1152; i += 256) {
            int tap = i >> 7, u = i & 127;
            uint4 v = gw4[((ch*9 + tap)*2 + cg)*128 + u];
            *(uint4*)(Ws + tap*2048 + u*16) = v;
        }
        __syncthreads();

#pragma unroll
        for (int tap = 0; tap < 9; ++tap) {
            const int kh = tap/3, kw = tap - kh*3;
            const char* wb = Ws + tap*2048 + l*8;
#pragma unroll
            for (int i = 0; i < 2; ++i) {
                uint32_t aaddr = Ab[i] + kh*3072 + kw*48;
                uint32_t a0, a1, a2, a3;
                asm volatile(
                    "ldmatrix.sync.aligned.m8n8.x4.shared.b16 {%0,%1,%2,%3}, [%4];"
                    : "=r"(a0), "=r"(a1), "=r"(a2), "=r"(a3) : "r"(aaddr));
#pragma unroll
                for (int j = 0; j < 8; ++j) {
                    uint2 bb = *(const uint2*)(wb + j*256);
                    asm volatile(
                        "mma.sync.aligned.m16n8k32.row.col.s32.s8.s8.s32 "
                        "{%0,%1,%2,%3},{%4,%5,%6,%7},{%8,%9},{%0,%1,%2,%3};"
                        : "+r"(c[i][j][0]), "+r"(c[i][j][1]),
                          "+r"(c[i][j][2]), "+r"(c[i][j][3])
                        : "r"(a0), "r"(a1), "r"(a2), "r"(a3),
                          "r"(bb.x), "r"(bb.y));
                }
            }
        }
    }
    __syncthreads();

    if (PHASE == 0) {
        // requant int8, stage [h 4][w' 64][ci 64], store 2 packed chunks
        uint16_t* Yb = (uint16_t*)smem;
#pragma unroll
        for (int i = 0; i < 2; ++i)
#pragma unroll
            for (int j = 0; j < 8; ++j) {
                int nn = j*8 + (l & 3)*2;
#pragma unroll
                for (int half = 0; half < 2; ++half) {
                    int p = ws*32 + i*16 + (l >> 2) + half*8;
                    int q0 = (int)rintf(fminf((float)max(c[i][j][half*2  ], 0)*(1.f/64.f), 127.f));
                    int q1 = (int)rintf(fminf((float)max(c[i][j][half*2+1], 0)*(1.f/64.f), 127.f));
                    Yb[((hh*64 + p)*64 + nn) >> 1] =
                        (uint16_t)((q0 & 255) | ((q1 & 255) << 8));
                }
            }
        __syncthreads();
        uint4* gy = (uint4*)g_y1q;
        for (int i = t; i < 1024; i += 256) {
            int hr = i >> 8, rem = i & 255;
            int w = rem >> 2, u = rem & 3;
            uint4 v = make_uint4(0,0,0,0);
            if (w >= 1 && w <= 56)
                v = *(const uint4*)(smem + ((hr*64 + w)*64 + u*16));
            gy[((((n*4 + cg*2 + (u >> 1))*HH_ + h0 + hr)*64 + w) << 1) + (u & 1)] = v;
        }
    } else {
        // residual add @ scale 2^11, clamp, relu -> fp32 NCHW; 4 passes x 16 couts
        float* Fst = (float*)smem;             // [co 16] stride 264, [h 4] stride 66
        for (int pass = 0; pass < 4; ++pass) {
#pragma unroll
            for (int j2 = 0; j2 < 2; ++j2) {
                int j = pass*2 + j2;
#pragma unroll
                for (int i = 0; i < 2; ++i) {
                    int nloc = j2*8 + (l & 3)*2;
                    int p0 = ws*32 + i*16 + (l >> 2);
                    Fst[ nloc   *264 + hh*66 + p0    ] = (float)c[i][j][0];
                    Fst[(nloc+1)*264 + hh*66 + p0    ] = (float)c[i][j][1];
                    Fst[ nloc   *264 + hh*66 + p0 + 8] = (float)c[i][j][2];
                    Fst[(nloc+1)*264 + hh*66 + p0 + 8] = (float)c[i][j][3];
                }
            }
            __syncthreads();
            for (int i = t; i < 16*4*56; i += 256) {
                int co = i / 224, rem = i - co*224;
                int hr = rem / 56, w = rem - hr*56;
                float d = Fst[co*264 + hr*66 + w + 1];
                int gi = ((n*CC + cg*64 + pass*16 + co)*HH_ + h0 + hr)*WW_ + w;
                float s = d + xres[gi]*2048.0f;
                s = fminf(fmaxf(s, -2147483647.0f), 2147483647.0f);
                out[gi] = fmaxf(s, 0.0f) * (1.0f/2048.0f);
            }
            __syncthreads();
        }
    }
}

// ---------------- launch -----------------------------------------------------
extern "C" void kernel_launch(void* const* d_in, const int* in_sizes, int n_in,
                              void* d_out, int out_size) {
    const float* x  = (const float*)d_in[0];
    const float* w1 = (const float*)d_in[1];
    const float* w2 = (const float*)d_in[2];
    float* out = (float*)d_out;

    prep_x<<<dim3(HH_, NB), 256>>>(x);
    prep_w<<<(2*4*9*2*8*32*2 + 255)/256, 256>>>(w1, w2);

    dim3 grid(14, 2, 32);
    conv_imma<0><<<grid, 256>>>(nullptr, nullptr);
    conv_imma<1><<<grid, 256>>>(x, out);
}

// round 16
// speedup vs baseline: 1.9350x; 1.9350x over previous
#include <cuda_runtime.h>
#include <cuda_bf16.h>
#include <cstdint>

#define NB   32
#define CC   128
#define HH_  56
#define WW_  56

// activations int8, packed: [n][chunk 4][h 56][w' 64][ci 32] (w'=w+1, zero cols 0,57-63)
__device__ uint32_t g_xq [NB*4*HH_*64*8];
__device__ uint32_t g_y1q[NB*4*HH_*64*8];
// weights int8, PRE-PERMUTED for per-lane LDS.64 B fragments:
// [T 2][ch 4][tap 9][cg 4][j 4][lane 32][2 words]
__device__ uint32_t g_wq [2*4*9*4*4*32*2];

// ---------------- prep: quantize x -> packed int8 ---------------------------
__global__ void prep_x(const float* __restrict__ x) {
    __shared__ char s[CC][WW_];
    const int h = blockIdx.x, n = blockIdx.y, t = threadIdx.x;
    for (int i = t; i < CC*WW_; i += 256) {
        int c = i / WW_, w = i % WW_;
        float v = x[((n*CC + c)*HH_ + h)*WW_ + w];
        s[c][w] = (char)(int)rintf(fminf(fmaxf(v * 32.0f, -128.0f), 127.0f));
    }
    __syncthreads();
    for (int i = t; i < 4*64*8; i += 256) {
        int u = i & 7, wp = (i >> 3) & 63, ch = i >> 9;
        uint32_t word = 0;
        if (wp >= 1 && wp <= 56) {
            int ci = ch*32 + u*4, w = wp - 1;
            word = ((uint32_t)(uint8_t)s[ci][w])
                 | ((uint32_t)(uint8_t)s[ci+1][w] << 8)
                 | ((uint32_t)(uint8_t)s[ci+2][w] << 16)
                 | ((uint32_t)(uint8_t)s[ci+3][w] << 24);
        }
        g_xq[(((n*4 + ch)*HH_ + h)*64 + wp)*8 + u] = word;
    }
}

// ---------------- prep: weights OIHW f32 -> permuted int8 fragments ---------
// word index e -> [T][ch][tap][cg][j][lane l][w2]
__global__ void prep_w(const float* __restrict__ w1, const float* __restrict__ w2s) {
    int e = blockIdx.x*256 + threadIdx.x;
    if (e >= 2*4*9*4*4*32*2) return;
    int w2 = e & 1, l = (e >> 1) & 31, j = (e >> 6) & 3, cg = (e >> 8) & 3;
    int g  = e >> 10;
    int tap = g % 9, ch = (g / 9) & 3, T = g / 36;
    const float* w = T ? w2s : w1;
    int co = cg*32 + j*8 + (l >> 2);
    int ciw = (l & 3) + w2*4;                 // 32-bit word within 32-byte k
    uint32_t word = 0;
#pragma unroll
    for (int b = 0; b < 4; ++b) {
        int ci = ch*32 + ciw*4 + b;
        int q = (int)rintf(w[(co*CC + ci)*9 + tap]);
        word |= (uint32_t)(q & 255) << (8*b);
    }
    g_wq[e] = word;
}

// ---------------- conv core: int8 mma m16n8k32, occ-4, 256B/mma schedule ----
// block: n (z), cout-group of 32 (y), 4 h-rows (x of 14). 8 warps:
//   warp -> (row hh = wid>>1, w-half ws = wid&1), warp tile M=32 pix x N=32 cout
// per-tap: 2 ldmatrix (both A upfront) + 4 LDS.64 (B shared across i) + 8 mma.
static const int XS_BYTES = 6*64*48;           // 18432
static const int WS_BYTES = 9*4*32*8;          // 9216
static const int SM_BYTES = XS_BYTES + WS_BYTES;   // 27648 static

template <int PHASE>
__global__ void __launch_bounds__(256, 4)
conv_imma(const float* __restrict__ xres, float* __restrict__ out) {
    __shared__ __align__(16) char smem[SM_BYTES];
    char* Xs = smem;
    char* Ws = smem + XS_BYTES;
    const uint4* gin4 = (const uint4*)(PHASE == 0 ? g_xq : g_y1q);
    const uint4* gw4  = (const uint4*)g_wq + (size_t)PHASE*(4*9*4*256/4);

    const int n = blockIdx.z, cg = blockIdx.y, h0 = blockIdx.x*4;
    const int t = threadIdx.x, wid = t >> 5, l = t & 31;
    const int hh = wid >> 1, ws = wid & 1;
    const uint32_t Xu = (uint32_t)__cvta_generic_to_shared(Xs);

    // hoisted A addresses: ch/tap-invariant; per tap add kh*3072
    uint32_t A0[2][3];
#pragma unroll
    for (int i = 0; i < 2; ++i)
#pragma unroll
        for (int kw = 0; kw < 3; ++kw) {
            int p = min(max(ws*32 + i*16 + (l & 15) + kw - 1, 0), 63);
            A0[i][kw] = Xu + (hh*64 + p)*48 + (l >> 4)*16;
        }

    int c[2][4][4];
#pragma unroll
    for (int i = 0; i < 2; ++i)
#pragma unroll
        for (int j = 0; j < 4; ++j)
#pragma unroll
            for (int k = 0; k < 4; ++k) c[i][j][k] = 0;

    for (int ch = 0; ch < 4; ++ch) {
        __syncthreads();
        // stage X: 6 rows (h0-1 .. h0+4) x 64 w', 32B/pixel -> 48B rows
        for (int i = t; i < 384; i += 256) {
            int hr = i >> 6, w = i & 63;
            int h = h0 + hr - 1;
            uint4 v0 = make_uint4(0,0,0,0), v1 = v0;
            if (h >= 0 && h < HH_) {
                const uint4* p = gin4 + ((((n*4 + ch)*HH_ + h)*64 + w) << 1);
                v0 = p[0]; v1 = p[1];
            }
            char* d = Xs + (hr*64 + w)*48;
            *(uint4*)d        = v0;
            *(uint4*)(d + 16) = v1;
        }
        // stage W: contiguous permuted fragments, 64 uint4 per tap
        for (int i = t; i < 576; i += 256) {
            int tap = i >> 6, u = i & 63;
            uint4 v = gw4[((ch*9 + tap)*4 + cg)*64 + u];
            *(uint4*)(Ws + tap*1024 + u*16) = v;
        }
        __syncthreads();

#pragma unroll
        for (int tap = 0; tap < 9; ++tap) {
            const int kh = tap/3, kw = tap - kh*3;
            const char* wb = Ws + tap*1024 + l*8;
            // both A fragments upfront (back-to-back ldmatrix, ILP)
            uint32_t a[2][4];
#pragma unroll
            for (int i = 0; i < 2; ++i) {
                uint32_t aaddr = A0[i][kw] + kh*3072;
                asm volatile(
                    "ldmatrix.sync.aligned.m8n8.x4.shared.b16 {%0,%1,%2,%3}, [%4];"
                    : "=r"(a[i][0]), "=r"(a[i][1]), "=r"(a[i][2]), "=r"(a[i][3])
                    : "r"(aaddr));
            }
            // one LDS.64 per j, shared across both i
#pragma unroll
            for (int j = 0; j < 4; ++j) {
                uint2 bb = *(const uint2*)(wb + j*256);
#pragma unroll
                for (int i = 0; i < 2; ++i)
                    asm volatile(
                        "mma.sync.aligned.m16n8k32.row.col.s32.s8.s8.s32 "
                        "{%0,%1,%2,%3},{%4,%5,%6,%7},{%8,%9},{%0,%1,%2,%3};"
                        : "+r"(c[i][j][0]), "+r"(c[i][j][1]),
                          "+r"(c[i][j][2]), "+r"(c[i][j][3])
                        : "r"(a[i][0]), "r"(a[i][1]), "r"(a[i][2]), "r"(a[i][3]),
                          "r"(bb.x), "r"(bb.y));
            }
        }
    }
    __syncthreads();

    if (PHASE == 0) {
        // requant int8, stage [h 4][w' 64][ci 32], store packed
        uint16_t* Yb = (uint16_t*)smem;
#pragma unroll
        for (int i = 0; i < 2; ++i)
#pragma unroll
            for (int j = 0; j < 4; ++j) {
                int nn = j*8 + (l & 3)*2;
#pragma unroll
                for (int half = 0; half < 2; ++half) {
                    int p = ws*32 + i*16 + (l >> 2) + half*8;
                    int q0 = (int)rintf(fminf((float)max(c[i][j][half*2  ], 0)*(1.f/64.f), 127.f));
                    int q1 = (int)rintf(fminf((float)max(c[i][j][half*2+1], 0)*(1.f/64.f), 127.f));
                    Yb[((hh*64 + p)*32 + nn) >> 1] =
                        (uint16_t)((q0 & 255) | ((q1 & 255) << 8));
                }
            }
        __syncthreads();
        uint4* gy = (uint4*)g_y1q;
        for (int i = t; i < 256; i += 256) {
            int hr = i >> 6, w = i & 63;
            uint4 v0 = make_uint4(0,0,0,0), v1 = v0;
            if (w >= 1 && w <= 56) {
                const uint4* p = (const uint4*)(smem + (hr*64 + w)*32);
                v0 = p[0]; v1 = p[1];
            }
            uint4* d = gy + ((((n*4 + cg)*HH_ + h0 + hr)*64 + w) << 1);
            d[0] = v0; d[1] = v1;
        }
    } else {
        // residual add @ scale 2^11, clamp, relu -> fp32 NCHW; 2 passes x 16 couts
        float* Fst = (float*)smem;             // [co 16] stride 264, [h 4] stride 66
        for (int pass = 0; pass < 2; ++pass) {
#pragma unroll
            for (int j2 = 0; j2 < 2; ++j2) {
                int j = pass*2 + j2;
#pragma unroll
                for (int i = 0; i < 2; ++i) {
                    int nloc = j2*8 + (l & 3)*2;
                    int p0 = ws*32 + i*16 + (l >> 2);
                    Fst[ nloc   *264 + hh*66 + p0    ] = (float)c[i][j][0];
                    Fst[(nloc+1)*264 + hh*66 + p0    ] = (float)c[i][j][1];
                    Fst[ nloc   *264 + hh*66 + p0 + 8] = (float)c[i][j][2];
                    Fst[(nloc+1)*264 + hh*66 + p0 + 8] = (float)c[i][j][3];
                }
            }
            __syncthreads();
            for (int i = t; i < 16*4*56; i += 256) {
                int co = i / 224, rem = i - co*224;
                int hr = rem / 56, w = rem - hr*56;
                float d = Fst[co*264 + hr*66 + w + 1];
                int gi = ((n*CC + cg*32 + pass*16 + co)*HH_ + h0 + hr)*WW_ + w;
                float s = d + xres[gi]*2048.0f;
                s = fminf(fmaxf(s, -2147483647.0f), 2147483647.0f);
                out[gi] = fmaxf(s, 0.0f) * (1.0f/2048.0f);
            }
            __syncthreads();
        }
    }
}

// ---------------- launch -----------------------------------------------------
extern "C" void kernel_launch(void* const* d_in, const int* in_sizes, int n_in,
                              void* d_out, int out_size) {
    const float* x  = (const float*)d_in[0];
    const float* w1 = (const float*)d_in[1];
    const float* w2 = (const float*)d_in[2];
    float* out = (float*)d_out;

    prep_x<<<dim3(HH_, NB), 256>>>(x);
    prep_w<<<(2*4*9*4*4*32*2 + 255)/256, 256>>>(w1, w2);

    dim3 grid(14, 4, 32);
    conv_imma<0><<<grid, 256>>>(nullptr, nullptr);
    conv_imma<1><<<grid, 256>>>(x, out);
}